// round 10
// baseline (speedup 1.0000x reference)
#include <cuda_runtime.h>
#include <cuda_bf16.h>
#include <cstdint>

#define N_ROWS 1024
#define PPARTS 8
#define DFEAT  2048
#define DX     18432   /* 9 * 2048 */
#define MARGIN 0.3f

// ---- GEMM tiling ----
#define TB      128                 /* tile M = N */
#define BK      64                  /* k per stage (128 B rows -> SW128 swizzle) */
#define KSPLIT  8
#define KCHUNK  (DX / KSPLIT)       /* 2304 */
#define NT_CTA  (KCHUNK / BK)       /* 36 stages */
#define NSTAGE  3
#define TILE_BYTES  (TB * BK * 2)           /* 16384 */
#define STAGE_BYTES (2 * TILE_BYTES)        /* 32768: A then B */
#define B_OFF   TILE_BYTES
#define DYN_SMEM (NSTAGE * STAGE_BYTES)     /* 96 KB (also reused as epilogue buffer) */
#define N_TRI   36                  /* 8*9/2 upper-triangular tiles */
#define NBLOCKS (N_TRI * KSPLIT)    /* 288 CTAs -> 2 per SM */

// ---- device scratch ----
__device__ __align__(16) __nv_bfloat16 g_X[N_ROWS * DX];        // ~37.7 MB
__device__ __align__(16) float g_part[N_TRI * KSPLIT * TB * TB]; // 18.9 MB partials
__device__ __align__(16) float g_dist[N_ROWS * N_ROWS];          // 4 MB final dist
__device__ unsigned g_mask[N_ROWS];
__device__ float    g_rowloss[N_ROWS];
__device__ int      g_cnt[N_TRI];       // zero-init; reset by reducer each launch
__device__ int      g_cnt_mine;         // zero-init; reset by last mine block

// =================== PTX helpers ===================
__device__ __forceinline__ uint32_t smem_u32(const void* p) {
    uint32_t a;
    asm("{ .reg .u64 t; cvta.to.shared.u64 t, %1; cvt.u32.u64 %0, t; }"
        : "=r"(a) : "l"(p));
    return a;
}
__device__ __forceinline__ void cp_async16_u(uint32_t saddr, const void* g) {
    asm volatile("cp.async.cg.shared.global [%0], [%1], 16;\n" :: "r"(saddr), "l"(g));
}
__device__ __forceinline__ void ldsm_x4_u(uint32_t* r, uint32_t addr) {
    asm volatile("ldmatrix.sync.aligned.m8n8.x4.shared.b16 {%0,%1,%2,%3}, [%4];\n"
        : "=r"(r[0]), "=r"(r[1]), "=r"(r[2]), "=r"(r[3]) : "r"(addr));
}
__device__ __forceinline__ void mma16816(float* c, const uint32_t* a, const uint32_t* b) {
    asm volatile(
        "mma.sync.aligned.m16n8k16.row.col.f32.bf16.bf16.f32 "
        "{%0,%1,%2,%3}, {%4,%5,%6,%7}, {%8,%9}, {%0,%1,%2,%3};\n"
        : "+f"(c[0]), "+f"(c[1]), "+f"(c[2]), "+f"(c[3])
        : "r"(a[0]), "r"(a[1]), "r"(a[2]), "r"(a[3]), "r"(b[0]), "r"(b[1]));
}
__device__ __forceinline__ uint32_t swz(uint32_t off) {
    return off ^ ((off >> 3) & 0x70);
}

// ================= Kernel 1: normalize + build X (bf16) + masks ==============
__global__ __launch_bounds__(256) void prep_kernel(
    const float* __restrict__ gfeat, const float* __restrict__ pfeat,
    const float* __restrict__ plab)
{
    const int row  = blockIdx.x / 9;
    const int part = blockIdx.x % 9;
    const int tid  = threadIdx.x;

    if (part == 0 && tid == 0) {    // fused packmask
        unsigned m = 0;
        #pragma unroll
        for (int p = 0; p < PPARTS; ++p)
            if (plab[row * PPARTS + p] > 0.5f) m |= (1u << p);
        g_mask[row] = m;
    }

    const float* src = (part == 0) ? (gfeat + (size_t)row * DFEAT)
                                   : (pfeat + ((size_t)row * PPARTS + (part - 1)) * DFEAT);
    const float4* s4 = (const float4*)src;

    float4 v0 = s4[tid];
    float4 v1 = s4[tid + 256];

    float ss = v0.x * v0.x + v0.y * v0.y + v0.z * v0.z + v0.w * v0.w
             + v1.x * v1.x + v1.y * v1.y + v1.z * v1.z + v1.w * v1.w;
    #pragma unroll
    for (int o = 16; o > 0; o >>= 1) ss += __shfl_xor_sync(0xFFFFFFFFu, ss, o);

    __shared__ float wss[8];
    if ((tid & 31) == 0) wss[tid >> 5] = ss;
    __syncthreads();
    float tot = wss[0] + wss[1] + wss[2] + wss[3] + wss[4] + wss[5] + wss[6] + wss[7];

    float scale = 1.0f / (sqrtf(tot) + 1e-12f);
    if (part > 0) scale *= plab[row * PPARTS + (part - 1)];   // 0.0 or 1.0

    __nv_bfloat162* d2 = (__nv_bfloat162*)(g_X + (size_t)row * DX + part * DFEAT);
    __nv_bfloat162 a, b;
    a.x = __float2bfloat16(v0.x * scale); a.y = __float2bfloat16(v0.y * scale);
    b.x = __float2bfloat16(v0.z * scale); b.y = __float2bfloat16(v0.w * scale);
    d2[2 * tid]       = a;
    d2[2 * tid + 1]   = b;
    a.x = __float2bfloat16(v1.x * scale); a.y = __float2bfloat16(v1.y * scale);
    b.x = __float2bfloat16(v1.z * scale); b.y = __float2bfloat16(v1.w * scale);
    d2[2 * (tid + 256)]     = a;
    d2[2 * (tid + 256) + 1] = b;
}

// ======= Kernel 2: HMMA GEMM + in-kernel cross-CTA reduction to dist =========
extern __shared__ char dynsmem[];

__device__ __forceinline__ void fill_stage(uint32_t sbase, int stage,
                                           int bm, int bn, int k0, int tid) {
    const uint32_t ab = sbase + stage * STAGE_BYTES;
    const uint32_t bb = ab + B_OFF;
    #pragma unroll
    for (int j = 0; j < 4; ++j) {
        int id = tid + 256 * j;
        int r  = id >> 3;
        int ce = (id & 7) * 8;
        cp_async16_u(ab + swz((uint32_t)(r * 128 + ce * 2)),
                     &g_X[(size_t)(bm + r) * DX + k0 + ce]);
    }
    #pragma unroll
    for (int j = 0; j < 4; ++j) {
        int id = tid + 256 * j;
        int r  = id >> 3;
        int ce = (id & 7) * 8;
        cp_async16_u(bb + swz((uint32_t)(r * 128 + ce * 2)),
                     &g_X[(size_t)(bn + r) * DX + k0 + ce]);
    }
    asm volatile("cp.async.commit_group;\n");
}

__device__ __forceinline__ void ld_frags(uint32_t ab, uint32_t bb, int wm, int wn,
                                         int lane, int ks,
                                         uint32_t (*areg)[4], uint32_t (*breg)[4]) {
    const uint32_t colbA = (uint32_t)(ks * 32 + ((lane >> 4) << 4));
    const uint32_t colbB = (uint32_t)(ks * 32 + (((lane >> 3) & 1) << 4));
    #pragma unroll
    for (int mf = 0; mf < 4; ++mf) {
        const uint32_t row = (uint32_t)(wm + mf * 16 + (lane & 15));
        ldsm_x4_u(areg[mf], ab + swz(row * 128 + colbA));
    }
    #pragma unroll
    for (int nq = 0; nq < 2; ++nq) {
        const uint32_t row = (uint32_t)(wn + nq * 16 + (lane & 7) + ((lane >> 4) << 3));
        ldsm_x4_u(breg[nq], bb + swz(row * 128 + colbB));
    }
}

__global__ __launch_bounds__(256, 2) void gemm_kernel() {
    __shared__ unsigned msA[TB], msB[TB];
    __shared__ int s_red;

    const int tid  = threadIdx.x;
    const int wid  = tid >> 5;
    const int lane = tid & 31;

    int blk = blockIdx.x;
    const int split   = blk % KSPLIT;
    const int tile_id = blk / KSPLIT;
    int b = tile_id, ti = 0;
    while (b >= 8 - ti) { b -= 8 - ti; ++ti; }
    const int tj = ti + b;
    const int bm = ti * TB, bn = tj * TB;
    const int kbase = split * KCHUNK;

    const uint32_t sbase = smem_u32(dynsmem);

    if (tid < TB) { msA[tid] = g_mask[bm + tid]; msB[tid] = g_mask[bn + tid]; }
    if (tid == 0) s_red = 0;

    // 8 warps: 2(M) x 4(N) grid of 64x32 warp tiles
    const int wm = (wid & 1) * 64;
    const int wn = (wid >> 1) * 32;

    float acc[4][4][4];
    #pragma unroll
    for (int mf = 0; mf < 4; ++mf)
        #pragma unroll
        for (int nf = 0; nf < 4; ++nf)
            #pragma unroll
            for (int e = 0; e < 4; ++e) acc[mf][nf][e] = 0.0f;

    fill_stage(sbase, 0, bm, bn, kbase, tid);
    fill_stage(sbase, 1, bm, bn, kbase + BK, tid);

    for (int kt = 0; kt < NT_CTA; ++kt) {
        if (kt == NT_CTA - 1) asm volatile("cp.async.wait_group 0;\n");
        else                  asm volatile("cp.async.wait_group 1;\n");
        __syncthreads();

        if (kt + 2 < NT_CTA)
            fill_stage(sbase, (kt + 2) % NSTAGE, bm, bn, kbase + (kt + 2) * BK, tid);

        const uint32_t ab = sbase + (kt % NSTAGE) * STAGE_BYTES;
        const uint32_t bb = ab + B_OFF;

        uint32_t areg[2][4][4], breg[2][2][4];
        ld_frags(ab, bb, wm, wn, lane, 0, areg[0], breg[0]);
        #pragma unroll
        for (int ks = 0; ks < 4; ++ks) {
            const int cur = ks & 1;
            if (ks < 3)
                ld_frags(ab, bb, wm, wn, lane, ks + 1, areg[cur ^ 1], breg[cur ^ 1]);
            #pragma unroll
            for (int mf = 0; mf < 4; ++mf)
                #pragma unroll
                for (int nf = 0; nf < 4; ++nf)
                    mma16816(acc[mf][nf], areg[cur][mf],
                             &breg[cur][nf >> 1][(nf & 1) * 2]);
        }
    }
    __syncthreads();   // smem stages done; reuse as staging buffer

    // ---- stage acc into smem (stride 132 floats, 16B aligned rows) ----
    float* Ds = (float*)dynsmem;
    const int r0 = wm + (lane >> 2);
    const int c0 = wn + ((lane & 3) << 1);
    #pragma unroll
    for (int mf = 0; mf < 4; ++mf)
        #pragma unroll
        for (int h = 0; h < 2; ++h) {
            const int r = r0 + mf * 16 + h * 8;
            #pragma unroll
            for (int nf = 0; nf < 4; ++nf) {
                #pragma unroll
                for (int e = 0; e < 2; ++e)
                    Ds[r * 132 + c0 + nf * 8 + e] = acc[mf][nf][h * 2 + e];
            }
        }
    __syncthreads();

    // ---- write this split's raw partial (coalesced, no mirror) ----
    float* Pout = g_part + ((size_t)(tile_id * KSPLIT + split)) * (TB * TB);
    #pragma unroll
    for (int it = 0; it < 16; ++it) {
        const int vid = it * 256 + tid;
        const int r = vid >> 5, c4 = (vid & 31) * 4;
        *(float4*)&Pout[r * TB + c4] = *(const float4*)&Ds[r * 132 + c4];
    }

    // ---- tree handoff: last CTA of the 8 splits reduces to dist ----
    __threadfence();
    __syncthreads();
    if (tid == 0) {
        if (atomicAdd(&g_cnt[tile_id], 1) == KSPLIT - 1) s_red = 1;
    }
    __syncthreads();
    if (!s_red) return;

    // reducer path (1 CTA per tile): sum 8 partials in fixed order, epilogue
    const float* pb = g_part + (size_t)tile_id * (KSPLIT * TB * TB);
    #pragma unroll 4
    for (int it = 0; it < 16; ++it) {
        const int vid = it * 256 + tid;
        const int r = vid >> 5, c4 = (vid & 31) * 4;
        float4 s = make_float4(0.f, 0.f, 0.f, 0.f);
        #pragma unroll
        for (int sp = 0; sp < KSPLIT; ++sp) {
            const float4 v = __ldcg((const float4*)(pb + (size_t)sp * (TB * TB) + r * TB + c4));
            s.x += v.x; s.y += v.y; s.z += v.z; s.w += v.w;
        }
        const unsigned mi = msA[r];
        float4 dv;
        {
            float o0 = (float)__popc(mi & msB[c4 + 0]) + 1.0f;
            float o1 = (float)__popc(mi & msB[c4 + 1]) + 1.0f;
            float o2 = (float)__popc(mi & msB[c4 + 2]) + 1.0f;
            float o3 = (float)__popc(mi & msB[c4 + 3]) + 1.0f;
            dv.x = (o0 - s.x) * (0.5f / o0);
            dv.y = (o1 - s.y) * (0.5f / o1);
            dv.z = (o2 - s.z) * (0.5f / o2);
            dv.w = (o3 - s.w) * (0.5f / o3);
        }
        *(float4*)&g_dist[(size_t)(bm + r) * N_ROWS + bn + c4] = dv;
        *(float4*)&Ds[r * 132 + c4] = dv;
    }
    __syncthreads();
    if (ti != tj) {
        #pragma unroll 4
        for (int it = 0; it < 16; ++it) {
            const int vid = it * 256 + tid;
            const int c = vid >> 5, r4 = (vid & 31) * 4;
            float4 v;
            v.x = Ds[(r4 + 0) * 132 + c];
            v.y = Ds[(r4 + 1) * 132 + c];
            v.z = Ds[(r4 + 2) * 132 + c];
            v.w = Ds[(r4 + 3) * 132 + c];
            *(float4*)&g_dist[(size_t)(bn + c) * N_ROWS + bm + r4] = v;
        }
    }
    if (tid == 0) g_cnt[tile_id] = 0;   // reset for next graph replay
}

// ===== Kernel 3: hard mining + mean (labels decoded in-kernel, fused) ========
__global__ __launch_bounds__(256) void mine_kernel(const int* __restrict__ w,
                                                   float* __restrict__ out) {
    __shared__ int   sl[N_ROWS];
    __shared__ float sap[8], san[8];
    __shared__ int   s_is64, s_last;
    const int tid = threadIdx.x;
    const int i   = blockIdx.x;

    if (tid == 0) { s_is64 = 1; s_last = 0; }
    __syncthreads();
    for (int j = tid; j < N_ROWS; j += 256)
        if (w[2 * j + 1] != 0) s_is64 = 0;
    __syncthreads();
    const int is64 = s_is64;
    for (int j = tid; j < N_ROWS; j += 256)
        sl[j] = is64 ? w[2 * j] : w[j];
    __syncthreads();

    const int li = sl[i];
    float ap = -1e30f, an = 1e30f;
    const int j0 = tid * 4;
    const float4 dv4 = *(const float4*)&g_dist[(size_t)i * N_ROWS + j0];
    const float dvv[4] = { dv4.x, dv4.y, dv4.z, dv4.w };
    #pragma unroll
    for (int e = 0; e < 4; ++e) {
        if (sl[j0 + e] == li) ap = fmaxf(ap, dvv[e]);
        else                  an = fminf(an, dvv[e]);
    }
    #pragma unroll
    for (int o = 16; o > 0; o >>= 1) {
        ap = fmaxf(ap, __shfl_xor_sync(0xFFFFFFFFu, ap, o));
        an = fminf(an, __shfl_xor_sync(0xFFFFFFFFu, an, o));
    }
    if ((tid & 31) == 0) { sap[tid >> 5] = ap; san[tid >> 5] = an; }
    __syncthreads();
    if (tid == 0) {
        float fap = sap[0], fan = san[0];
        #pragma unroll
        for (int wdx = 1; wdx < 8; ++wdx) {
            fap = fmaxf(fap, sap[wdx]);
            fan = fminf(fan, san[wdx]);
        }
        g_rowloss[i] = fmaxf(0.0f, fap - fan + MARGIN);
        __threadfence();
        if (atomicAdd(&g_cnt_mine, 1) == N_ROWS - 1) s_last = 1;
    }
    __syncthreads();
    if (!s_last) return;

    // last block: mean over g_rowloss
    float v = 0.0f;
    for (int j = tid; j < N_ROWS; j += 256) v += __ldcg(&g_rowloss[j]);
    #pragma unroll
    for (int o = 16; o > 0; o >>= 1) v += __shfl_xor_sync(0xFFFFFFFFu, v, o);
    __shared__ float ws[8];
    if ((tid & 31) == 0) ws[tid >> 5] = v;
    __syncthreads();
    if (tid == 0) {
        float t = ws[0] + ws[1] + ws[2] + ws[3] + ws[4] + ws[5] + ws[6] + ws[7];
        out[0] = t * (1.0f / (float)N_ROWS);
        g_cnt_mine = 0;   // reset for next graph replay
    }
}

// ================= launcher ==================================================
extern "C" void kernel_launch(void* const* d_in, const int* in_sizes, int n_in,
                              void* d_out, int out_size) {
    const float* gfeat = (const float*)d_in[0];
    const float* pfeat = (const float*)d_in[1];
    const float* plab  = (const float*)d_in[2];
    const int*   glabw = (const int*)d_in[3];   // int32 OR int64 words; detected on device
    float*       out   = (float*)d_out;

    static int cfg_done = 0;
    if (!cfg_done) {
        cudaFuncSetAttribute(gemm_kernel,
                             cudaFuncAttributeMaxDynamicSharedMemorySize, DYN_SMEM);
        cfg_done = 1;
    }

    prep_kernel<<<N_ROWS * 9, 256>>>(gfeat, pfeat, plab);
    gemm_kernel<<<NBLOCKS, 256, DYN_SMEM>>>();
    mine_kernel<<<N_ROWS, 256>>>(glabw, out);
}

// round 12
// speedup vs baseline: 1.2677x; 1.2677x over previous
#include <cuda_runtime.h>
#include <cuda_bf16.h>
#include <cstdint>

#define N_ROWS 1024
#define PPARTS 8
#define DFEAT  2048
#define DX     18432   /* 9 * 2048 */
#define MARGIN 0.3f

// ---- GEMM tiling (round-9 proven config) ----
#define TB      128
#define BK      64
#define KSPLIT  8
#define KCHUNK  (DX / KSPLIT)       /* 2304 */
#define NT_CTA  (KCHUNK / BK)       /* 36 stages */
#define NSTAGE  3
#define TILE_BYTES  (TB * BK * 2)           /* 16384 */
#define STAGE_BYTES (2 * TILE_BYTES)        /* 32768: A then B */
#define B_OFF   TILE_BYTES
#define DYN_SMEM (NSTAGE * STAGE_BYTES)     /* 96 KB */
#define N_TRI   36
#define NBLOCKS (N_TRI * KSPLIT)    /* 288 CTAs -> 2 per SM */

// ---- mine tiling ----
#define MROWS   8                   /* rows per mine block */
#define MBLOCKS (N_ROWS / MROWS)    /* 128 */

// ---- device scratch ----
__device__ __align__(16) __nv_bfloat16 g_X[N_ROWS * DX];       // ~37.7 MB
__device__ __align__(16) float g_S4[KSPLIT * N_ROWS * N_ROWS]; // 32 MB partial dots
__device__ unsigned g_mask[N_ROWS];
__device__ float    g_rowloss[N_ROWS];
__device__ int      g_cnt_mine;     // zero-init; reset by last mine block

// =================== PTX helpers ===================
__device__ __forceinline__ uint32_t smem_u32(const void* p) {
    uint32_t a;
    asm("{ .reg .u64 t; cvta.to.shared.u64 t, %1; cvt.u32.u64 %0, t; }"
        : "=r"(a) : "l"(p));
    return a;
}
__device__ __forceinline__ void cp_async16_u(uint32_t saddr, const void* g) {
    asm volatile("cp.async.cg.shared.global [%0], [%1], 16;\n" :: "r"(saddr), "l"(g));
}
__device__ __forceinline__ void ldsm_x4_u(uint32_t* r, uint32_t addr) {
    asm volatile("ldmatrix.sync.aligned.m8n8.x4.shared.b16 {%0,%1,%2,%3}, [%4];\n"
        : "=r"(r[0]), "=r"(r[1]), "=r"(r[2]), "=r"(r[3]) : "r"(addr));
}
__device__ __forceinline__ void mma16816(float* c, const uint32_t* a, const uint32_t* b) {
    asm volatile(
        "mma.sync.aligned.m16n8k16.row.col.f32.bf16.bf16.f32 "
        "{%0,%1,%2,%3}, {%4,%5,%6,%7}, {%8,%9}, {%0,%1,%2,%3};\n"
        : "+f"(c[0]), "+f"(c[1]), "+f"(c[2]), "+f"(c[3])
        : "r"(a[0]), "r"(a[1]), "r"(a[2]), "r"(a[3]), "r"(b[0]), "r"(b[1]));
}
__device__ __forceinline__ uint32_t swz(uint32_t off) {
    return off ^ ((off >> 3) & 0x70);
}

// ================= Kernel 1: normalize + build X (bf16) + masks ==============
__global__ __launch_bounds__(256) void prep_kernel(
    const float* __restrict__ gfeat, const float* __restrict__ pfeat,
    const float* __restrict__ plab)
{
    const int row  = blockIdx.x / 9;
    const int part = blockIdx.x % 9;
    const int tid  = threadIdx.x;

    if (part == 0 && tid == 0) {    // fused packmask
        unsigned m = 0;
        #pragma unroll
        for (int p = 0; p < PPARTS; ++p)
            if (plab[row * PPARTS + p] > 0.5f) m |= (1u << p);
        g_mask[row] = m;
    }

    const float* src = (part == 0) ? (gfeat + (size_t)row * DFEAT)
                                   : (pfeat + ((size_t)row * PPARTS + (part - 1)) * DFEAT);
    const float4* s4 = (const float4*)src;

    // streaming (evict-first) reads: inputs are read exactly once
    float4 v0 = __ldcs(&s4[tid]);
    float4 v1 = __ldcs(&s4[tid + 256]);

    float ss = v0.x * v0.x + v0.y * v0.y + v0.z * v0.z + v0.w * v0.w
             + v1.x * v1.x + v1.y * v1.y + v1.z * v1.z + v1.w * v1.w;
    #pragma unroll
    for (int o = 16; o > 0; o >>= 1) ss += __shfl_xor_sync(0xFFFFFFFFu, ss, o);

    __shared__ float wss[8];
    if ((tid & 31) == 0) wss[tid >> 5] = ss;
    __syncthreads();
    float tot = wss[0] + wss[1] + wss[2] + wss[3] + wss[4] + wss[5] + wss[6] + wss[7];

    float scale = 1.0f / (sqrtf(tot) + 1e-12f);
    if (part > 0) scale *= plab[row * PPARTS + (part - 1)];   // 0.0 or 1.0

    __nv_bfloat162* d2 = (__nv_bfloat162*)(g_X + (size_t)row * DX + part * DFEAT);
    __nv_bfloat162 a, b;
    a.x = __float2bfloat16(v0.x * scale); a.y = __float2bfloat16(v0.y * scale);
    b.x = __float2bfloat16(v0.z * scale); b.y = __float2bfloat16(v0.w * scale);
    d2[2 * tid]       = a;
    d2[2 * tid + 1]   = b;
    a.x = __float2bfloat16(v1.x * scale); a.y = __float2bfloat16(v1.y * scale);
    b.x = __float2bfloat16(v1.z * scale); b.y = __float2bfloat16(v1.w * scale);
    d2[2 * (tid + 256)]     = a;
    d2[2 * (tid + 256) + 1] = b;
}

// ================= Kernel 2: HMMA GEMM, triangular + 8-way K-split ===========
// (verbatim round-9 structure: 256 threads, 8 warps 2x4 of 64x32, 2 CTAs/SM)
extern __shared__ char dynsmem[];

__device__ __forceinline__ void fill_stage(uint32_t sbase, int stage,
                                           int bm, int bn, int k0, int tid) {
    const uint32_t ab = sbase + stage * STAGE_BYTES;
    const uint32_t bb = ab + B_OFF;
    #pragma unroll
    for (int j = 0; j < 4; ++j) {
        int id = tid + 256 * j;
        int r  = id >> 3;
        int ce = (id & 7) * 8;
        cp_async16_u(ab + swz((uint32_t)(r * 128 + ce * 2)),
                     &g_X[(size_t)(bm + r) * DX + k0 + ce]);
    }
    #pragma unroll
    for (int j = 0; j < 4; ++j) {
        int id = tid + 256 * j;
        int r  = id >> 3;
        int ce = (id & 7) * 8;
        cp_async16_u(bb + swz((uint32_t)(r * 128 + ce * 2)),
                     &g_X[(size_t)(bn + r) * DX + k0 + ce]);
    }
    asm volatile("cp.async.commit_group;\n");
}

__device__ __forceinline__ void ld_frags(uint32_t ab, uint32_t bb, int wm, int wn,
                                         int lane, int ks,
                                         uint32_t (*areg)[4], uint32_t (*breg)[4]) {
    const uint32_t colbA = (uint32_t)(ks * 32 + ((lane >> 4) << 4));
    const uint32_t colbB = (uint32_t)(ks * 32 + (((lane >> 3) & 1) << 4));
    #pragma unroll
    for (int mf = 0; mf < 4; ++mf) {
        const uint32_t row = (uint32_t)(wm + mf * 16 + (lane & 15));
        ldsm_x4_u(areg[mf], ab + swz(row * 128 + colbA));
    }
    #pragma unroll
    for (int nq = 0; nq < 2; ++nq) {
        const uint32_t row = (uint32_t)(wn + nq * 16 + (lane & 7) + ((lane >> 4) << 3));
        ldsm_x4_u(breg[nq], bb + swz(row * 128 + colbB));
    }
}

__global__ __launch_bounds__(256, 2) void gemm_kernel() {
    const int tid  = threadIdx.x;
    const int wid  = tid >> 5;
    const int lane = tid & 31;

    int blk = blockIdx.x;
    const int split = blk % KSPLIT;
    int b = blk / KSPLIT, ti = 0;
    while (b >= 8 - ti) { b -= 8 - ti; ++ti; }
    const int tj = ti + b;
    const int bm = ti * TB, bn = tj * TB;
    const int kbase = split * KCHUNK;

    const uint32_t sbase = smem_u32(dynsmem);

    const int wm = (wid & 1) * 64;
    const int wn = (wid >> 1) * 32;

    float acc[4][4][4];
    #pragma unroll
    for (int mf = 0; mf < 4; ++mf)
        #pragma unroll
        for (int nf = 0; nf < 4; ++nf)
            #pragma unroll
            for (int e = 0; e < 4; ++e) acc[mf][nf][e] = 0.0f;

    fill_stage(sbase, 0, bm, bn, kbase, tid);
    fill_stage(sbase, 1, bm, bn, kbase + BK, tid);

    for (int kt = 0; kt < NT_CTA; ++kt) {
        if (kt == NT_CTA - 1) asm volatile("cp.async.wait_group 0;\n");
        else                  asm volatile("cp.async.wait_group 1;\n");
        __syncthreads();

        if (kt + 2 < NT_CTA)
            fill_stage(sbase, (kt + 2) % NSTAGE, bm, bn, kbase + (kt + 2) * BK, tid);

        const uint32_t ab = sbase + (kt % NSTAGE) * STAGE_BYTES;
        const uint32_t bb = ab + B_OFF;

        uint32_t areg[2][4][4], breg[2][2][4];
        ld_frags(ab, bb, wm, wn, lane, 0, areg[0], breg[0]);
        #pragma unroll
        for (int ks = 0; ks < 4; ++ks) {
            const int cur = ks & 1;
            if (ks < 3)
                ld_frags(ab, bb, wm, wn, lane, ks + 1, areg[cur ^ 1], breg[cur ^ 1]);
            #pragma unroll
            for (int mf = 0; mf < 4; ++mf)
                #pragma unroll
                for (int nf = 0; nf < 4; ++nf)
                    mma16816(acc[mf][nf], areg[cur][mf],
                             &breg[cur][nf >> 1][(nf & 1) * 2]);
        }
    }
    __syncthreads();   // smem stages done; reuse as epilogue buffer

    float* Ds = (float*)dynsmem;
    const int r0 = wm + (lane >> 2);
    const int c0 = wn + ((lane & 3) << 1);
    #pragma unroll
    for (int mf = 0; mf < 4; ++mf)
        #pragma unroll
        for (int h = 0; h < 2; ++h) {
            const int r = r0 + mf * 16 + h * 8;
            #pragma unroll
            for (int nf = 0; nf < 4; ++nf) {
                #pragma unroll
                for (int e = 0; e < 2; ++e)
                    Ds[r * 132 + c0 + nf * 8 + e] = acc[mf][nf][h * 2 + e];
            }
        }
    __syncthreads();

    float* Sout = g_S4 + ((size_t)split << 20);
    #pragma unroll
    for (int it = 0; it < 16; ++it) {
        const int vid = it * 256 + tid;
        const int r = vid >> 5, c4 = (vid & 31) * 4;
        float4 v = *(const float4*)&Ds[r * 132 + c4];
        *(float4*)&Sout[(size_t)(bm + r) * N_ROWS + bn + c4] = v;
    }
    if (ti != tj) {
        #pragma unroll
        for (int it = 0; it < 16; ++it) {
            const int vid = it * 256 + tid;
            const int c = vid >> 5, r4 = (vid & 31) * 4;
            float4 v;
            v.x = Ds[(r4 + 0) * 132 + c];
            v.y = Ds[(r4 + 1) * 132 + c];
            v.z = Ds[(r4 + 2) * 132 + c];
            v.w = Ds[(r4 + 3) * 132 + c];
            *(float4*)&Sout[(size_t)(bn + c) * N_ROWS + bm + r4] = v;
        }
    }
}

// ==== Kernel 3: combine partials + dist + mining + mean (8 rows/block) =======
__global__ __launch_bounds__(512) void mine_kernel(const int* __restrict__ w,
                                                   float* __restrict__ out) {
    __shared__ int      sl[N_ROWS];
    __shared__ unsigned smk[N_ROWS];
    __shared__ float    sap[16], san[16];
    __shared__ int      s_is64, s_last;
    const int tid = threadIdx.x;
    const int i0  = blockIdx.x * MROWS;

    if (tid == 0) { s_is64 = 1; s_last = 0; }
    __syncthreads();
    if (tid < N_ROWS / 2 && w[2 * tid + 1] != 0) s_is64 = 0;
    __syncthreads();
    const int is64 = s_is64;
    sl[tid]        = is64 ? w[2 * tid]           : w[tid];
    sl[tid + 512]  = is64 ? w[2 * (tid + 512)]   : w[tid + 512];
    smk[tid]       = g_mask[tid];
    smk[tid + 512] = g_mask[tid + 512];
    __syncthreads();

    const int c0 = tid * 2;                       // 512 threads x 2 cols
    const unsigned mk0 = smk[c0], mk1 = smk[c0 + 1];
    const int      lb0 = sl[c0],  lb1 = sl[c0 + 1];

    for (int r = 0; r < MROWS; ++r) {
        const int i = i0 + r;
        const int      li = sl[i];
        const unsigned mi = smk[i];
        const size_t   ro = (size_t)i * N_ROWS + c0;

        float sx = 0.f, sy = 0.f;
        #pragma unroll
        for (int sp = 0; sp < KSPLIT; ++sp) {
            const float2 v = __ldcg((const float2*)&g_S4[((size_t)sp << 20) + ro]);
            sx += v.x; sy += v.y;
        }
        const float o0 = (float)__popc(mi & mk0) + 1.0f;
        const float o1 = (float)__popc(mi & mk1) + 1.0f;
        const float d0 = (o0 - sx) * (0.5f / o0);
        const float d1 = (o1 - sy) * (0.5f / o1);

        float ap = -1e30f, an = 1e30f;
        if (lb0 == li) ap = fmaxf(ap, d0); else an = fminf(an, d0);
        if (lb1 == li) ap = fmaxf(ap, d1); else an = fminf(an, d1);
        #pragma unroll
        for (int o = 16; o > 0; o >>= 1) {
            ap = fmaxf(ap, __shfl_xor_sync(0xFFFFFFFFu, ap, o));
            an = fminf(an, __shfl_xor_sync(0xFFFFFFFFu, an, o));
        }
        if ((tid & 31) == 0) { sap[tid >> 5] = ap; san[tid >> 5] = an; }
        __syncthreads();
        if (tid == 0) {
            float fap = sap[0], fan = san[0];
            #pragma unroll
            for (int wd = 1; wd < 16; ++wd) {
                fap = fmaxf(fap, sap[wd]);
                fan = fminf(fan, san[wd]);
            }
            g_rowloss[i] = fmaxf(0.0f, fap - fan + MARGIN);
        }
        __syncthreads();
    }

    if (tid == 0) {
        __threadfence();
        if (atomicAdd(&g_cnt_mine, 1) == MBLOCKS - 1) s_last = 1;
    }
    __syncthreads();
    if (!s_last) return;

    // last block: mean over g_rowloss
    float v = __ldcg(&g_rowloss[tid]) + __ldcg(&g_rowloss[tid + 512]);
    #pragma unroll
    for (int o = 16; o > 0; o >>= 1) v += __shfl_xor_sync(0xFFFFFFFFu, v, o);
    __shared__ float ws[16];
    if ((tid & 31) == 0) ws[tid >> 5] = v;
    __syncthreads();
    if (tid == 0) {
        float t = 0.f;
        #pragma unroll
        for (int wd = 0; wd < 16; ++wd) t += ws[wd];
        out[0] = t * (1.0f / (float)N_ROWS);
        g_cnt_mine = 0;   // reset for next graph replay
    }
}

// ================= launcher ==================================================
extern "C" void kernel_launch(void* const* d_in, const int* in_sizes, int n_in,
                              void* d_out, int out_size) {
    const float* gfeat = (const float*)d_in[0];
    const float* pfeat = (const float*)d_in[1];
    const float* plab  = (const float*)d_in[2];
    const int*   glabw = (const int*)d_in[3];   // int32 OR int64 words; detected on device
    float*       out   = (float*)d_out;

    static int cfg_done = 0;
    if (!cfg_done) {
        cudaFuncSetAttribute(gemm_kernel,
                             cudaFuncAttributeMaxDynamicSharedMemorySize, DYN_SMEM);
        cfg_done = 1;
    }

    prep_kernel<<<N_ROWS * 9, 256>>>(gfeat, pfeat, plab);
    gemm_kernel<<<NBLOCKS, 256, DYN_SMEM>>>();
    mine_kernel<<<MBLOCKS, 512>>>(glabw, out);
}